// round 15
// baseline (speedup 1.0000x reference)
#include <cuda_runtime.h>
#include <cuda_bf16.h>
#include <cuda_fp16.h>
#include <math.h>
#include <stdint.h>

#define NN 512
#define CC 3
#define PIX 1024
#define FF 3072          // K dim
#define HH 4
#define HF 12288         // N dim
#define EE 4096
#define ET 4608
#define BEPS 1e-5f
#define SLOPE 0.2f

// GEMM tiling: CTA 128x128, 4 warps (64x64 warp tile), 2 CTAs/SM
#define BM 128
#define BN 128
#define BK 64
#define NK (FF / BK)             // 48
#define NHALF 6144               // N columns per half
#define TILES_HALF ((NN / BM) * (NHALF / BN))    // 4 * 48 = 192

// smem stage layout (fp16, padded rows for conflict-free ldmatrix)
#define A_STRIDE 144             // 64 halves = 128 B + 16 pad
#define B_STRIDE 272             // 128 halves = 256 B + 16 pad
#define OFF_A 0
#define OFF_B (BM * A_STRIDE)                    // 18432
#define STAGE_BYTES (OFF_B + BK * B_STRIDE)      // 35840
#define NSTAGE 3
#define SMEM_TOTAL (NSTAGE * STAGE_BYTES)        // 107520 -> 2 CTAs/SM

// logits kernel smem: xr cache + logits buffer
#define LS_CAP 128
#define LS_SMEM (HF * 4 + HH * LS_CAP * 4)       // 51200

// ---------------- scratch ----------------------------------------------------
__device__ __half d_Ah[NN * FF];
__device__ __half d_Bl16[(size_t)FF * HF];
__device__ __half d_Br16[(size_t)FF * HF];
__device__ float d_xl[(size_t)NN * HF];
__device__ float d_xr[(size_t)NN * HF];
__device__ float d_alpha[ET * HH];
__device__ float d_agg[(size_t)NN * HF];
__device__ int   d_rowptr[NN + 1];
__device__ int   d_esrc[ET];

// ---------------- PTX helpers ------------------------------------------------
__device__ __forceinline__ uint32_t smem_to_u32(const void* p) {
    uint32_t a;
    asm("{ .reg .u64 t; cvta.to.shared.u64 t, %1; cvt.u32.u64 %0, t; }" : "=r"(a) : "l"(p));
    return a;
}
__device__ __forceinline__ void cpa16(uint32_t dst, const void* src) {
    asm volatile("cp.async.cg.shared.global [%0], [%1], 16;" :: "r"(dst), "l"(src));
}
#define CP_COMMIT() asm volatile("cp.async.commit_group;" ::: "memory")
#define CP_WAIT0()  asm volatile("cp.async.wait_group 0;" ::: "memory")
#define CP_WAIT1()  asm volatile("cp.async.wait_group 1;" ::: "memory")

#define LDSM_X4(r0, r1, r2, r3, addr) \
    asm volatile("ldmatrix.sync.aligned.m8n8.x4.shared.b16 {%0,%1,%2,%3}, [%4];" \
        : "=r"(r0), "=r"(r1), "=r"(r2), "=r"(r3) : "r"(addr))
#define LDSM_X4T(r0, r1, r2, r3, addr) \
    asm volatile("ldmatrix.sync.aligned.m8n8.x4.trans.shared.b16 {%0,%1,%2,%3}, [%4];" \
        : "=r"(r0), "=r"(r1), "=r"(r2), "=r"(r3) : "r"(addr))

#define MMA16816F16(d, a, b) \
    asm volatile("mma.sync.aligned.m16n8k16.row.col.f32.f16.f16.f32 " \
        "{%0,%1,%2,%3}, {%4,%5,%6,%7}, {%8,%9}, {%0,%1,%2,%3};" \
        : "+f"((d)[0]), "+f"((d)[1]), "+f"((d)[2]), "+f"((d)[3]) \
        : "r"((a)[0]), "r"((a)[1]), "r"((a)[2]), "r"((a)[3]), "r"((b)[0]), "r"((b)[1]))

// ---------------- misc -------------------------------------------------------
__device__ __forceinline__ int edge_src(const int* ei, int e) { return (e < EE) ? ei[e] : (e - EE); }
__device__ __forceinline__ int edge_dst(const int* ei, int e) { return (e < EE) ? ei[EE + e] : (e - EE); }

// ---------------- stage 1: fc1 + BN1 -> fp16 ---------------------------------
__global__ void fc1_bn_kernel(const float* __restrict__ x,
                              const float* __restrict__ W,
                              const float* __restrict__ b,
                              const float* __restrict__ bg,
                              const float* __restrict__ bb,
                              const float* __restrict__ bm,
                              const float* __restrict__ bv) {
    int n = blockIdx.x;
    int p = blockIdx.y * 256 + threadIdx.x;
    float xin[CC];
#pragma unroll
    for (int c = 0; c < CC; c++) xin[c] = x[(size_t)n * FF + c * PIX + p];
#pragma unroll
    for (int oc = 0; oc < CC; oc++) {
        float t = b[oc];
#pragma unroll
        for (int ic = 0; ic < CC; ic++) t += W[oc * CC + ic] * xin[ic];
        float inv = bg[oc] * rsqrtf(bv[oc] + BEPS);
        float hv = t * inv + bb[oc] - bm[oc] * inv;
        d_Ah[(size_t)n * FF + oc * PIX + p] = __float2half_rn(hv);
    }
}

// ---------------- weight fp32 -> fp16 convert (N-column half per launch) -----
// converts W[:, c0:c0+NHALF]; 8 floats per thread, 768 thread-slots per row.
__global__ void wconv_kernel(const float* __restrict__ W, int which, int c0) {
    __half* B = which ? d_Br16 : d_Bl16;
    size_t idx = (size_t)blockIdx.x * 256 + threadIdx.x;
    size_t row = idx / (NHALF / 8);
    size_t col = (idx % (NHALF / 8)) * 8 + c0;
    size_t i = row * HF + col;
    float4 v0 = *(const float4*)(W + i);
    float4 v1 = *(const float4*)(W + i + 4);
    __half2 h[4];
    h[0] = __floats2half2_rn(v0.x, v0.y);
    h[1] = __floats2half2_rn(v0.z, v0.w);
    h[2] = __floats2half2_rn(v1.x, v1.y);
    h[3] = __floats2half2_rn(v1.z, v1.w);
    *(uint4*)(B + i) = *(uint4*)h;
}

// ---------------- CSR build: init + deg + scan + scatter, one CTA ------------
__global__ void __launch_bounds__(512)
csr_kernel(const int* __restrict__ ei) {
    __shared__ int sdeg[NN];
    __shared__ int sscan[NN];
    __shared__ int scur[NN];
    int t = threadIdx.x;
    sdeg[t] = 0;
    __syncthreads();
    for (int e = t; e < ET; e += NN) atomicAdd(&sdeg[edge_dst(ei, e)], 1);
    __syncthreads();
    sscan[t] = sdeg[t];
    __syncthreads();
    for (int o = 1; o < NN; o <<= 1) {
        int v = (t >= o) ? sscan[t - o] : 0;
        __syncthreads();
        sscan[t] += v;
        __syncthreads();
    }
    if (t == 0) d_rowptr[0] = 0;
    d_rowptr[t + 1] = sscan[t];
    scur[t] = sscan[t] - sdeg[t];
    __syncthreads();
    for (int e = t; e < ET; e += NN) {
        int slot = atomicAdd(&scur[edge_dst(ei, e)], 1);
        d_esrc[slot] = edge_src(ei, e);
    }
}

// ---------------- stage 2: HMMA GEMM (3-stage, single sync per chunk) --------
__device__ __forceinline__ void load_stage(uint32_t st, int m0, int n0, int k0,
                                           const __half* __restrict__ B, int tid) {
#pragma unroll
    for (int i = tid; i < 1024; i += 128) {
        int row = i >> 3, c = i & 7;
        uint32_t off = row * A_STRIDE + c * 16;
        size_t g = (size_t)(m0 + row) * FF + k0 + c * 8;
        cpa16(st + OFF_A + off, d_Ah + g);
    }
#pragma unroll
    for (int i = tid; i < 1024; i += 128) {
        int row = i >> 4, c = i & 15;
        uint32_t off = row * B_STRIDE + c * 16;
        size_t g = (size_t)(k0 + row) * HF + n0 + c * 8;
        cpa16(st + OFF_B + off, B + g);
    }
}

__global__ void __launch_bounds__(128, 2)
mmagemm_kernel(const float* __restrict__ biasL, const float* __restrict__ biasR,
               int gemm, int nbase) {
    extern __shared__ __align__(1024) char smem[];
    uint32_t sbase = smem_to_u32(smem);
    int tid = threadIdx.x;
    int wid = tid >> 5, lane = tid & 31;

    int r = blockIdx.x;
    int n0 = nbase + (r >> 2) * BN;
    int m0 = (r & 3) * BM;

    const __half* B = gemm ? d_Br16 : d_Bl16;
    float* C = gemm ? d_xr : d_xl;
    const float* bias = gemm ? biasR : biasL;

    // warp tile 64 (M) x 64 (N): 2 warps in M, 2 warps in N
    int wm = (wid & 1) * 64;
    int wn = (wid >> 1) * 64;

    uint32_t stg[NSTAGE];
#pragma unroll
    for (int s = 0; s < NSTAGE; s++) stg[s] = sbase + s * STAGE_BYTES;

    float acc[4][8][4];
#pragma unroll
    for (int mf = 0; mf < 4; mf++)
#pragma unroll
        for (int nf = 0; nf < 8; nf++)
#pragma unroll
            for (int q = 0; q < 4; q++) acc[mf][nf][q] = 0.0f;

    load_stage(stg[0], m0, n0, 0, B, tid);
    CP_COMMIT();
    load_stage(stg[1], m0, n0, BK, B, tid);
    CP_COMMIT();

    uint32_t a_lrow = (lane & 7) + ((lane >> 3) & 1) * 8;
    uint32_t a_kadd = (lane >> 4) * 16;
    uint32_t b_lrow = (lane & 7) + ((lane >> 3) & 1) * 8;
    uint32_t b_nadd = (lane >> 4) * 16;

    uint32_t ah[2][4][4], bh[2][8][2];

    for (int kt = 0; kt < NK; kt++) {
        if (kt + 1 < NK) { CP_WAIT1(); } else { CP_WAIT0(); }
        __syncthreads();
        if (kt + 2 < NK) {
            load_stage(stg[(kt + 2) % NSTAGE], m0, n0, (kt + 2) * BK, B, tid);
            CP_COMMIT();
        }

        uint32_t st = stg[kt % NSTAGE];
        uint32_t abase = st + OFF_A + (wm + a_lrow) * A_STRIDE + a_kadd;
        uint32_t bbase = st + OFF_B + b_lrow * B_STRIDE + wn * 2 + b_nadd;

#pragma unroll
        for (int mf = 0; mf < 4; mf++)
            LDSM_X4(ah[0][mf][0], ah[0][mf][1], ah[0][mf][2], ah[0][mf][3],
                    abase + mf * 16 * A_STRIDE);
#pragma unroll
        for (int c = 0; c < 4; c++)
            LDSM_X4T(bh[0][2 * c][0], bh[0][2 * c][1], bh[0][2 * c + 1][0], bh[0][2 * c + 1][1],
                     bbase + c * 32);

#pragma unroll
        for (int kks = 0; kks < 4; kks++) {
            int cur = kks & 1, nxt = cur ^ 1;
            if (kks < 3) {
                uint32_t ab = abase + (kks + 1) * 32;
                uint32_t bb = bbase + (kks + 1) * 16 * B_STRIDE;
#pragma unroll
                for (int mf = 0; mf < 4; mf++)
                    LDSM_X4(ah[nxt][mf][0], ah[nxt][mf][1], ah[nxt][mf][2], ah[nxt][mf][3],
                            ab + mf * 16 * A_STRIDE);
#pragma unroll
                for (int c = 0; c < 4; c++)
                    LDSM_X4T(bh[nxt][2 * c][0], bh[nxt][2 * c][1],
                             bh[nxt][2 * c + 1][0], bh[nxt][2 * c + 1][1],
                             bb + c * 32);
            }
#pragma unroll
            for (int mf = 0; mf < 4; mf++)
#pragma unroll
                for (int nf = 0; nf < 8; nf++)
                    MMA16816F16(acc[mf][nf], ah[cur][mf], bh[cur][nf]);
        }
    }

    // epilogue
    int g = lane >> 2, tc = lane & 3;
#pragma unroll
    for (int mf = 0; mf < 4; mf++) {
#pragma unroll
        for (int nf = 0; nf < 8; nf++) {
            int row = m0 + wm + mf * 16 + g;
            int col = n0 + wn + nf * 8 + tc * 2;
            float b0 = bias[col], b1 = bias[col + 1];
            float2 v0 = make_float2(acc[mf][nf][0] + b0, acc[mf][nf][1] + b1);
            float2 v1 = make_float2(acc[mf][nf][2] + b0, acc[mf][nf][3] + b1);
            *(float2*)(C + (size_t)row * HF + col) = v0;
            *(float2*)(C + (size_t)(row + 8) * HF + col) = v1;
        }
    }
}

// ---------------- stage 3: fused logits + segment softmax (per dst) ----------
__global__ void __launch_bounds__(256)
logits_softmax_kernel(const float* __restrict__ att) {
    extern __shared__ float sm[];
    float* s_xr = sm;                 // HF floats
    float* s_lg = sm + HF;            // [HH][LS_CAP]
    int n = blockIdx.x, tid = threadIdx.x;
    int s0 = d_rowptr[n];
    int cnt = d_rowptr[n + 1] - s0;
    if (cnt > LS_CAP) cnt = LS_CAP;

    {
        const float4* xr = (const float4*)(d_xr + (size_t)n * HF);
        float4* sx = (float4*)s_xr;
        for (int i = tid; i < HF / 4; i += 256) sx[i] = xr[i];
    }
    __syncthreads();

    int wid = tid >> 5, lane = tid & 31;
    int h = wid & 3, ep = wid >> 2;
    for (int si = ep; si < cnt; si += 2) {
        int src = d_esrc[s0 + si];
        const float4* pl = (const float4*)(d_xl + (size_t)src * HF + h * FF);
        const float4* pr = (const float4*)(s_xr + h * FF);
        const float4* pa = (const float4*)(att + h * FF);
        float s = 0.0f;
#pragma unroll 4
        for (int it = 0; it < 24; it++) {
            int idx = lane + it * 32;
            float4 a = pl[idx];
            float4 b = pr[idx];
            float4 w = pa[idx];
            float z;
            z = a.x + b.x; s += w.x * (z > 0.0f ? z : SLOPE * z);
            z = a.y + b.y; s += w.y * (z > 0.0f ? z : SLOPE * z);
            z = a.z + b.z; s += w.z * (z > 0.0f ? z : SLOPE * z);
            z = a.w + b.w; s += w.w * (z > 0.0f ? z : SLOPE * z);
        }
#pragma unroll
        for (int o = 16; o; o >>= 1) s += __shfl_xor_sync(0xFFFFFFFFu, s, o);
        if (lane == 0) s_lg[h * LS_CAP + si] = s;
    }
    __syncthreads();

    if (wid < 4) {
        float* lg = s_lg + wid * LS_CAP;
        float mx = -INFINITY;
        for (int si = lane; si < cnt; si += 32) mx = fmaxf(mx, lg[si]);
#pragma unroll
        for (int o = 16; o; o >>= 1) mx = fmaxf(mx, __shfl_xor_sync(0xFFFFFFFFu, mx, o));
        float den = 0.0f;
        for (int si = lane; si < cnt; si += 32) {
            float ex = expf(lg[si] - mx);
            lg[si] = ex;
            den += ex;
        }
#pragma unroll
        for (int o = 16; o; o >>= 1) den += __shfl_xor_sync(0xFFFFFFFFu, den, o);
        float inv = 1.0f / den;
        for (int si = lane; si < cnt; si += 32)
            d_alpha[(s0 + si) * HH + wid] = lg[si] * inv;
    }
}

// ---------------- stage 5: aggregation ---------------------------------------
__global__ void __launch_bounds__(256)
agg_kernel() {
    __shared__ int   s_src[128];
    __shared__ float s_al[HH][128];
    int n = blockIdx.x, tid = threadIdx.x;
    int s0 = d_rowptr[n], s1 = d_rowptr[n + 1];

    float4 acc[12];
#pragma unroll
    for (int j = 0; j < 12; j++) acc[j] = make_float4(0.f, 0.f, 0.f, 0.f);

    for (int base = s0; base < s1; base += 128) {
        int cnt = min(128, s1 - base);
        __syncthreads();
        if (tid < cnt) {
            s_src[tid] = d_esrc[base + tid];
            float4 a = *(const float4*)(d_alpha + (size_t)(base + tid) * HH);
            s_al[0][tid] = a.x; s_al[1][tid] = a.y;
            s_al[2][tid] = a.z; s_al[3][tid] = a.w;
        }
        __syncthreads();
        for (int s = 0; s < cnt; s++) {
            const float4* row = (const float4*)(d_xl + (size_t)s_src[s] * HF);
            float al0 = s_al[0][s], al1 = s_al[1][s], al2 = s_al[2][s], al3 = s_al[3][s];
#pragma unroll
            for (int j = 0; j < 12; j++) {
                float al = (j < 3) ? al0 : (j < 6) ? al1 : (j < 9) ? al2 : al3;
                float4 v = row[j * 256 + tid];
                acc[j].x += al * v.x;
                acc[j].y += al * v.y;
                acc[j].z += al * v.z;
                acc[j].w += al * v.w;
            }
        }
    }

#pragma unroll
    for (int j = 0; j < 12; j++)
        *(float4*)(d_agg + (size_t)n * HF + (j * 256 + tid) * 4) = acc[j];
}

// ---------------- stage 6: fc2+BN2+residual + FFN (fused) --------------------
__global__ void final_kernel(const float* __restrict__ x,
                             const float* __restrict__ gat_b,
                             const float* __restrict__ fc2W, const float* __restrict__ fc2b,
                             const float* __restrict__ b2g, const float* __restrict__ b2b,
                             const float* __restrict__ b2m, const float* __restrict__ b2v,
                             const float* __restrict__ f1W, const float* __restrict__ f1b,
                             const float* __restrict__ bf1g, const float* __restrict__ bf1b,
                             const float* __restrict__ bf1m, const float* __restrict__ bf1v,
                             const float* __restrict__ f2W, const float* __restrict__ f2b,
                             const float* __restrict__ bf2g, const float* __restrict__ bf2b,
                             const float* __restrict__ bf2m, const float* __restrict__ bf2v,
                             float* __restrict__ out) {
    int n = blockIdx.x;
    int p = blockIdx.y * 256 + threadIdx.x;

    float ch[HH * CC];
#pragma unroll
    for (int h = 0; h < HH; h++)
#pragma unroll
        for (int c = 0; c < CC; c++)
            ch[h * CC + c] = d_agg[(size_t)n * HF + h * FF + c * PIX + p]
                           + gat_b[h * FF + c * PIX + p];

    float gv[CC];
#pragma unroll
    for (int oc = 0; oc < CC; oc++) {
        float t = fc2b[oc];
#pragma unroll
        for (int k = 0; k < HH * CC; k++) t += fc2W[oc * (HH * CC) + k] * ch[k];
        float inv = b2g[oc] * rsqrtf(b2v[oc] + BEPS);
        gv[oc] = t * inv + b2b[oc] - b2m[oc] * inv + x[(size_t)n * FF + oc * PIX + p];
    }
    float f1[CC];
#pragma unroll
    for (int oc = 0; oc < CC; oc++) {
        float t = f1b[oc];
#pragma unroll
        for (int ic = 0; ic < CC; ic++) t += f1W[oc * CC + ic] * gv[ic];
        float inv = bf1g[oc] * rsqrtf(bf1v[oc] + BEPS);
        float val = t * inv + bf1b[oc] - bf1m[oc] * inv;
        f1[oc] = val > 0.0f ? val : 0.0f;
    }
#pragma unroll
    for (int oc = 0; oc < CC; oc++) {
        float t = f2b[oc];
#pragma unroll
        for (int ic = 0; ic < CC; ic++) t += f2W[oc * CC + ic] * f1[ic];
        float inv = bf2g[oc] * rsqrtf(bf2v[oc] + BEPS);
        float val = t * inv + bf2b[oc] - bf2m[oc] * inv;
        out[(size_t)n * FF + oc * PIX + p] = val + gv[oc];
    }
}

// ---------------- launch -----------------------------------------------------
extern "C" void kernel_launch(void* const* d_in, const int* in_sizes, int n_in,
                              void* d_out, int out_size) {
    const float* x     = (const float*)d_in[0];
    const int*   ei    = (const int*)d_in[1];
    const float* fc1W  = (const float*)d_in[2];
    const float* fc1b  = (const float*)d_in[3];
    const float* b1g   = (const float*)d_in[4];
    const float* b1b   = (const float*)d_in[5];
    const float* b1m   = (const float*)d_in[6];
    const float* b1v   = (const float*)d_in[7];
    const float* Wl    = (const float*)d_in[8];
    const float* bl    = (const float*)d_in[9];
    const float* Wr    = (const float*)d_in[10];
    const float* br    = (const float*)d_in[11];
    const float* att   = (const float*)d_in[12];
    const float* gat_b = (const float*)d_in[13];
    const float* fc2W  = (const float*)d_in[14];
    const float* fc2b  = (const float*)d_in[15];
    const float* b2g   = (const float*)d_in[16];
    const float* b2b   = (const float*)d_in[17];
    const float* b2m   = (const float*)d_in[18];
    const float* b2v   = (const float*)d_in[19];
    const float* f1W   = (const float*)d_in[20];
    const float* f1b   = (const float*)d_in[21];
    const float* bf1g  = (const float*)d_in[22];
    const float* bf1b  = (const float*)d_in[23];
    const float* bf1m  = (const float*)d_in[24];
    const float* bf1v  = (const float*)d_in[25];
    const float* f2W   = (const float*)d_in[26];
    const float* f2b   = (const float*)d_in[27];
    const float* bf2g  = (const float*)d_in[28];
    const float* bf2b  = (const float*)d_in[29];
    const float* bf2m  = (const float*)d_in[30];
    const float* bf2v  = (const float*)d_in[31];
    float* out = (float*)d_out;

    // One-time host-side resource setup (streams/events; no device memory).
    static cudaStream_t sB = nullptr, sC = nullptr;
    static cudaEvent_t evFork, evL0, evL1, evR0, evFc1, evGemmR, evCsr;
    if (sB == nullptr) {
        cudaStreamCreateWithFlags(&sB, cudaStreamNonBlocking);
        cudaStreamCreateWithFlags(&sC, cudaStreamNonBlocking);
        cudaEventCreateWithFlags(&evFork,  cudaEventDisableTiming);
        cudaEventCreateWithFlags(&evL0,    cudaEventDisableTiming);
        cudaEventCreateWithFlags(&evL1,    cudaEventDisableTiming);
        cudaEventCreateWithFlags(&evR0,    cudaEventDisableTiming);
        cudaEventCreateWithFlags(&evFc1,   cudaEventDisableTiming);
        cudaEventCreateWithFlags(&evGemmR, cudaEventDisableTiming);
        cudaEventCreateWithFlags(&evCsr,   cudaEventDisableTiming);
        cudaFuncSetAttribute(mmagemm_kernel, cudaFuncAttributeMaxDynamicSharedMemorySize, SMEM_TOTAL);
        cudaFuncSetAttribute(logits_softmax_kernel, cudaFuncAttributeMaxDynamicSharedMemorySize, LS_SMEM);
    }

    const int WCONV_BLKS = (FF * NHALF) / (256 * 8);   // 9216

    // fork side streams off the capture (default) stream
    cudaEventRecord(evFork, 0);
    cudaStreamWaitEvent(sB, evFork, 0);
    cudaStreamWaitEvent(sC, evFork, 0);

    // side stream B: weight converts in N-halves, then gemm_R halves
    wconv_kernel<<<WCONV_BLKS, 256, 0, sB>>>(Wl, 0, 0);
    cudaEventRecord(evL0, sB);
    wconv_kernel<<<WCONV_BLKS, 256, 0, sB>>>(Wl, 0, NHALF);
    cudaEventRecord(evL1, sB);
    wconv_kernel<<<WCONV_BLKS, 256, 0, sB>>>(Wr, 1, 0);
    cudaEventRecord(evR0, sB);
    wconv_kernel<<<WCONV_BLKS, 256, 0, sB>>>(Wr, 1, NHALF);

    // side stream C: CSR build (only needed by logits)
    csr_kernel<<<1, NN, 0, sC>>>(ei);
    cudaEventRecord(evCsr, sC);

    // main stream: fc1, then gemm_L halves as their columns become ready
    fc1_bn_kernel<<<dim3(NN, 4), 256>>>(x, fc1W, fc1b, b1g, b1b, b1m, b1v);
    cudaEventRecord(evFc1, 0);
    cudaStreamWaitEvent(0, evL0, 0);
    mmagemm_kernel<<<TILES_HALF, 128, SMEM_TOTAL>>>(bl, br, 0, 0);
    cudaStreamWaitEvent(0, evL1, 0);
    mmagemm_kernel<<<TILES_HALF, 128, SMEM_TOTAL>>>(bl, br, 0, NHALF);

    // gemm_R halves on stream B (Wr converts are in program order on sB)
    cudaStreamWaitEvent(sB, evFc1, 0);
    cudaStreamWaitEvent(sB, evR0, 0);
    mmagemm_kernel<<<TILES_HALF, 128, SMEM_TOTAL, sB>>>(bl, br, 1, 0);
    mmagemm_kernel<<<TILES_HALF, 128, SMEM_TOTAL, sB>>>(bl, br, 1, NHALF);
    cudaEventRecord(evGemmR, sB);

    // join: logits needs gemm_L (program order), gemm_R and csr
    cudaStreamWaitEvent(0, evGemmR, 0);
    cudaStreamWaitEvent(0, evCsr, 0);
    logits_softmax_kernel<<<NN, 256, LS_SMEM>>>(att);
    agg_kernel<<<NN, 256>>>();
    final_kernel<<<dim3(NN, 4), 256>>>(x, gat_b, fc2W, fc2b, b2g, b2b, b2m, b2v,
                                       f1W, f1b, bf1g, bf1b, bf1m, bf1v,
                                       f2W, f2b, bf2g, bf2b, bf2m, bf2v, out);
}

// round 16
// speedup vs baseline: 1.1018x; 1.1018x over previous
#include <cuda_runtime.h>
#include <cuda_bf16.h>
#include <cuda_fp16.h>
#include <math.h>
#include <stdint.h>

#define NN 512
#define CC 3
#define PIX 1024
#define FF 3072          // K dim
#define HH 4
#define HF 12288         // N dim
#define EE 4096
#define ET 4608
#define BEPS 1e-5f
#define SLOPE 0.2f

// GEMM tiling: CTA 128x128, 4 warps (64x64 warp tile), 2 CTAs/SM
#define BM 128
#define BN 128
#define BK 64
#define NK (FF / BK)             // 48
#define TILES_PER_GEMM ((NN / BM) * (HF / BN))   // 384

// smem stage layout (fp16, padded rows for conflict-free ldmatrix)
#define A_STRIDE 144             // 64 halves = 128 B + 16 pad
#define B_STRIDE 272             // 128 halves = 256 B + 16 pad
#define OFF_A 0
#define OFF_B (BM * A_STRIDE)                    // 18432
#define STAGE_BYTES (OFF_B + BK * B_STRIDE)      // 35840
#define NSTAGE 3
#define SMEM_TOTAL (NSTAGE * STAGE_BYTES)        // 107520 -> 2 CTAs/SM

// fused logits+softmax+agg kernel smem
#define LS_CAP 128
#define LS_SMEM (HF * 4 + HH * LS_CAP * 4 + LS_CAP * 4)  // 49152+2048+512 = 51712

// ---------------- scratch ----------------------------------------------------
__device__ __half d_Ah[NN * FF];
__device__ __half d_Bl16[(size_t)FF * HF];
__device__ __half d_Br16[(size_t)FF * HF];
__device__ float d_xl[(size_t)NN * HF];
__device__ float d_xr[(size_t)NN * HF];
__device__ float d_agg[(size_t)NN * HF];
__device__ int   d_rowptr[NN + 1];
__device__ int   d_esrc[ET];

// ---------------- PTX helpers ------------------------------------------------
__device__ __forceinline__ uint32_t smem_to_u32(const void* p) {
    uint32_t a;
    asm("{ .reg .u64 t; cvta.to.shared.u64 t, %1; cvt.u32.u64 %0, t; }" : "=r"(a) : "l"(p));
    return a;
}
__device__ __forceinline__ void cpa16(uint32_t dst, const void* src) {
    asm volatile("cp.async.cg.shared.global [%0], [%1], 16;" :: "r"(dst), "l"(src));
}
#define CP_COMMIT() asm volatile("cp.async.commit_group;" ::: "memory")
#define CP_WAIT0()  asm volatile("cp.async.wait_group 0;" ::: "memory")
#define CP_WAIT1()  asm volatile("cp.async.wait_group 1;" ::: "memory")

#define LDSM_X4(r0, r1, r2, r3, addr) \
    asm volatile("ldmatrix.sync.aligned.m8n8.x4.shared.b16 {%0,%1,%2,%3}, [%4];" \
        : "=r"(r0), "=r"(r1), "=r"(r2), "=r"(r3) : "r"(addr))
#define LDSM_X4T(r0, r1, r2, r3, addr) \
    asm volatile("ldmatrix.sync.aligned.m8n8.x4.trans.shared.b16 {%0,%1,%2,%3}, [%4];" \
        : "=r"(r0), "=r"(r1), "=r"(r2), "=r"(r3) : "r"(addr))

#define MMA16816F16(d, a, b) \
    asm volatile("mma.sync.aligned.m16n8k16.row.col.f32.f16.f16.f32 " \
        "{%0,%1,%2,%3}, {%4,%5,%6,%7}, {%8,%9}, {%0,%1,%2,%3};" \
        : "+f"((d)[0]), "+f"((d)[1]), "+f"((d)[2]), "+f"((d)[3]) \
        : "r"((a)[0]), "r"((a)[1]), "r"((a)[2]), "r"((a)[3]), "r"((b)[0]), "r"((b)[1]))

// ---------------- misc -------------------------------------------------------
__device__ __forceinline__ int edge_src(const int* ei, int e) { return (e < EE) ? ei[e] : (e - EE); }
__device__ __forceinline__ int edge_dst(const int* ei, int e) { return (e < EE) ? ei[EE + e] : (e - EE); }

// ---------------- stage 1: fc1 + BN1 -> fp16 ---------------------------------
__global__ void fc1_bn_kernel(const float* __restrict__ x,
                              const float* __restrict__ W,
                              const float* __restrict__ b,
                              const float* __restrict__ bg,
                              const float* __restrict__ bb,
                              const float* __restrict__ bm,
                              const float* __restrict__ bv) {
    int n = blockIdx.x;
    int p = blockIdx.y * 256 + threadIdx.x;
    float xin[CC];
#pragma unroll
    for (int c = 0; c < CC; c++) xin[c] = x[(size_t)n * FF + c * PIX + p];
#pragma unroll
    for (int oc = 0; oc < CC; oc++) {
        float t = b[oc];
#pragma unroll
        for (int ic = 0; ic < CC; ic++) t += W[oc * CC + ic] * xin[ic];
        float inv = bg[oc] * rsqrtf(bv[oc] + BEPS);
        float hv = t * inv + bb[oc] - bm[oc] * inv;
        d_Ah[(size_t)n * FF + oc * PIX + p] = __float2half_rn(hv);
    }
}

// ---------------- weight fp32 -> fp16 convert (one matrix per launch) --------
__global__ void wconv_kernel(const float* __restrict__ W, int which) {
    __half* B = which ? d_Br16 : d_Bl16;
    size_t i = ((size_t)blockIdx.x * 256 + threadIdx.x) * 8;
    float4 v0 = *(const float4*)(W + i);
    float4 v1 = *(const float4*)(W + i + 4);
    __half2 h[4];
    h[0] = __floats2half2_rn(v0.x, v0.y);
    h[1] = __floats2half2_rn(v0.z, v0.w);
    h[2] = __floats2half2_rn(v1.x, v1.y);
    h[3] = __floats2half2_rn(v1.z, v1.w);
    *(uint4*)(B + i) = *(uint4*)h;
}

// ---------------- CSR build: init + deg + scan + scatter, one CTA ------------
__global__ void __launch_bounds__(512)
csr_kernel(const int* __restrict__ ei) {
    __shared__ int sdeg[NN];
    __shared__ int sscan[NN];
    __shared__ int scur[NN];
    int t = threadIdx.x;
    sdeg[t] = 0;
    __syncthreads();
    for (int e = t; e < ET; e += NN) atomicAdd(&sdeg[edge_dst(ei, e)], 1);
    __syncthreads();
    sscan[t] = sdeg[t];
    __syncthreads();
    for (int o = 1; o < NN; o <<= 1) {
        int v = (t >= o) ? sscan[t - o] : 0;
        __syncthreads();
        sscan[t] += v;
        __syncthreads();
    }
    if (t == 0) d_rowptr[0] = 0;
    d_rowptr[t + 1] = sscan[t];
    scur[t] = sscan[t] - sdeg[t];
    __syncthreads();
    for (int e = t; e < ET; e += NN) {
        int slot = atomicAdd(&scur[edge_dst(ei, e)], 1);
        d_esrc[slot] = edge_src(ei, e);
    }
}

// ---------------- stage 2: HMMA GEMM (3-stage, single sync per chunk) --------
__device__ __forceinline__ void load_stage(uint32_t st, int m0, int n0, int k0,
                                           const __half* __restrict__ B, int tid) {
#pragma unroll
    for (int i = tid; i < 1024; i += 128) {
        int row = i >> 3, c = i & 7;
        uint32_t off = row * A_STRIDE + c * 16;
        size_t g = (size_t)(m0 + row) * FF + k0 + c * 8;
        cpa16(st + OFF_A + off, d_Ah + g);
    }
#pragma unroll
    for (int i = tid; i < 1024; i += 128) {
        int row = i >> 4, c = i & 15;
        uint32_t off = row * B_STRIDE + c * 16;
        size_t g = (size_t)(k0 + row) * HF + n0 + c * 8;
        cpa16(st + OFF_B + off, B + g);
    }
}

__global__ void __launch_bounds__(128, 2)
mmagemm_kernel(const float* __restrict__ biasL, const float* __restrict__ biasR, int gemm) {
    extern __shared__ __align__(1024) char smem[];
    uint32_t sbase = smem_to_u32(smem);
    int tid = threadIdx.x;
    int wid = tid >> 5, lane = tid & 31;

    int r = blockIdx.x;
    int n0 = (r >> 2) * BN;
    int m0 = (r & 3) * BM;

    const __half* B = gemm ? d_Br16 : d_Bl16;
    float* C = gemm ? d_xr : d_xl;
    const float* bias = gemm ? biasR : biasL;

    // warp tile 64 (M) x 64 (N): 2 warps in M, 2 warps in N
    int wm = (wid & 1) * 64;
    int wn = (wid >> 1) * 64;

    uint32_t stg[NSTAGE];
#pragma unroll
    for (int s = 0; s < NSTAGE; s++) stg[s] = sbase + s * STAGE_BYTES;

    float acc[4][8][4];
#pragma unroll
    for (int mf = 0; mf < 4; mf++)
#pragma unroll
        for (int nf = 0; nf < 8; nf++)
#pragma unroll
            for (int q = 0; q < 4; q++) acc[mf][nf][q] = 0.0f;

    load_stage(stg[0], m0, n0, 0, B, tid);
    CP_COMMIT();
    load_stage(stg[1], m0, n0, BK, B, tid);
    CP_COMMIT();

    uint32_t a_lrow = (lane & 7) + ((lane >> 3) & 1) * 8;
    uint32_t a_kadd = (lane >> 4) * 16;
    uint32_t b_lrow = (lane & 7) + ((lane >> 3) & 1) * 8;
    uint32_t b_nadd = (lane >> 4) * 16;

    uint32_t ah[2][4][4], bh[2][8][2];

    for (int kt = 0; kt < NK; kt++) {
        if (kt + 1 < NK) { CP_WAIT1(); } else { CP_WAIT0(); }
        __syncthreads();
        if (kt + 2 < NK) {
            load_stage(stg[(kt + 2) % NSTAGE], m0, n0, (kt + 2) * BK, B, tid);
            CP_COMMIT();
        }

        uint32_t st = stg[kt % NSTAGE];
        uint32_t abase = st + OFF_A + (wm + a_lrow) * A_STRIDE + a_kadd;
        uint32_t bbase = st + OFF_B + b_lrow * B_STRIDE + wn * 2 + b_nadd;

#pragma unroll
        for (int mf = 0; mf < 4; mf++)
            LDSM_X4(ah[0][mf][0], ah[0][mf][1], ah[0][mf][2], ah[0][mf][3],
                    abase + mf * 16 * A_STRIDE);
#pragma unroll
        for (int c = 0; c < 4; c++)
            LDSM_X4T(bh[0][2 * c][0], bh[0][2 * c][1], bh[0][2 * c + 1][0], bh[0][2 * c + 1][1],
                     bbase + c * 32);

#pragma unroll
        for (int kks = 0; kks < 4; kks++) {
            int cur = kks & 1, nxt = cur ^ 1;
            if (kks < 3) {
                uint32_t ab = abase + (kks + 1) * 32;
                uint32_t bb = bbase + (kks + 1) * 16 * B_STRIDE;
#pragma unroll
                for (int mf = 0; mf < 4; mf++)
                    LDSM_X4(ah[nxt][mf][0], ah[nxt][mf][1], ah[nxt][mf][2], ah[nxt][mf][3],
                            ab + mf * 16 * A_STRIDE);
#pragma unroll
                for (int c = 0; c < 4; c++)
                    LDSM_X4T(bh[nxt][2 * c][0], bh[nxt][2 * c][1],
                             bh[nxt][2 * c + 1][0], bh[nxt][2 * c + 1][1],
                             bb + c * 32);
            }
#pragma unroll
            for (int mf = 0; mf < 4; mf++)
#pragma unroll
                for (int nf = 0; nf < 8; nf++)
                    MMA16816F16(acc[mf][nf], ah[cur][mf], bh[cur][nf]);
        }
    }

    // epilogue
    int g = lane >> 2, tc = lane & 3;
#pragma unroll
    for (int mf = 0; mf < 4; mf++) {
#pragma unroll
        for (int nf = 0; nf < 8; nf++) {
            int row = m0 + wm + mf * 16 + g;
            int col = n0 + wn + nf * 8 + tc * 2;
            float b0 = bias[col], b1 = bias[col + 1];
            float2 v0 = make_float2(acc[mf][nf][0] + b0, acc[mf][nf][1] + b1);
            float2 v1 = make_float2(acc[mf][nf][2] + b0, acc[mf][nf][3] + b1);
            *(float2*)(C + (size_t)row * HF + col) = v0;
            *(float2*)(C + (size_t)(row + 8) * HF + col) = v1;
        }
    }
}

// ---------------- stage 3: fused logits + softmax + aggregation (per dst) ----
__global__ void __launch_bounds__(256)
logits_softmax_agg_kernel(const float* __restrict__ att) {
    extern __shared__ float sm[];
    float* s_xr  = sm;                       // HF floats
    float* s_lg  = sm + HF;                  // [HH][LS_CAP]
    int*   s_src = (int*)(sm + HF + HH * LS_CAP);   // [LS_CAP]
    int n = blockIdx.x, tid = threadIdx.x;
    int s0 = d_rowptr[n];
    int cnt = d_rowptr[n + 1] - s0;
    if (cnt > LS_CAP) cnt = LS_CAP;

    // cache xr[n] and the src list
    {
        const float4* xr = (const float4*)(d_xr + (size_t)n * HF);
        float4* sx = (float4*)s_xr;
        for (int i = tid; i < HF / 4; i += 256) sx[i] = xr[i];
    }
    if (tid < cnt) s_src[tid] = d_esrc[s0 + tid];
    __syncthreads();

    int wid = tid >> 5, lane = tid & 31;
    int h = wid & 3, ep = wid >> 2;
    for (int si = ep; si < cnt; si += 2) {
        int src = s_src[si];
        const float4* pl = (const float4*)(d_xl + (size_t)src * HF + h * FF);
        const float4* pr = (const float4*)(s_xr + h * FF);
        const float4* pa = (const float4*)(att + h * FF);
        float s = 0.0f;
#pragma unroll 4
        for (int it = 0; it < 24; it++) {
            int idx = lane + it * 32;
            float4 a = pl[idx];
            float4 b = pr[idx];
            float4 w = pa[idx];
            float z;
            z = a.x + b.x; s += w.x * (z > 0.0f ? z : SLOPE * z);
            z = a.y + b.y; s += w.y * (z > 0.0f ? z : SLOPE * z);
            z = a.z + b.z; s += w.z * (z > 0.0f ? z : SLOPE * z);
            z = a.w + b.w; s += w.w * (z > 0.0f ? z : SLOPE * z);
        }
#pragma unroll
        for (int o = 16; o; o >>= 1) s += __shfl_xor_sync(0xFFFFFFFFu, s, o);
        if (lane == 0) s_lg[h * LS_CAP + si] = s;
    }
    __syncthreads();

    // softmax per head (warps 0..3); store normalized alpha back to smem
    if (wid < 4) {
        float* lg = s_lg + wid * LS_CAP;
        float mx = -INFINITY;
        for (int si = lane; si < cnt; si += 32) mx = fmaxf(mx, lg[si]);
#pragma unroll
        for (int o = 16; o; o >>= 1) mx = fmaxf(mx, __shfl_xor_sync(0xFFFFFFFFu, mx, o));
        float den = 0.0f;
        for (int si = lane; si < cnt; si += 32) {
            float ex = expf(lg[si] - mx);
            lg[si] = ex;
            den += ex;
        }
#pragma unroll
        for (int o = 16; o; o >>= 1) den += __shfl_xor_sync(0xFFFFFFFFu, den, o);
        float inv = 1.0f / den;
        for (int si = lane; si < cnt; si += 32) lg[si] *= inv;
    }
    __syncthreads();

    // aggregation: each thread accumulates 12 float4 (48 features)
    float4 acc[12];
#pragma unroll
    for (int j = 0; j < 12; j++) acc[j] = make_float4(0.f, 0.f, 0.f, 0.f);

    for (int si = 0; si < cnt; si++) {
        const float4* row = (const float4*)(d_xl + (size_t)s_src[si] * HF);
        float al0 = s_lg[0 * LS_CAP + si];
        float al1 = s_lg[1 * LS_CAP + si];
        float al2 = s_lg[2 * LS_CAP + si];
        float al3 = s_lg[3 * LS_CAP + si];
#pragma unroll
        for (int j = 0; j < 12; j++) {
            float al = (j < 3) ? al0 : (j < 6) ? al1 : (j < 9) ? al2 : al3;
            float4 v = row[j * 256 + tid];
            acc[j].x += al * v.x;
            acc[j].y += al * v.y;
            acc[j].z += al * v.z;
            acc[j].w += al * v.w;
        }
    }

#pragma unroll
    for (int j = 0; j < 12; j++)
        *(float4*)(d_agg + (size_t)n * HF + (j * 256 + tid) * 4) = acc[j];
}

// ---------------- stage 6: fc2+BN2+residual + FFN (fused) --------------------
__global__ void final_kernel(const float* __restrict__ x,
                             const float* __restrict__ gat_b,
                             const float* __restrict__ fc2W, const float* __restrict__ fc2b,
                             const float* __restrict__ b2g, const float* __restrict__ b2b,
                             const float* __restrict__ b2m, const float* __restrict__ b2v,
                             const float* __restrict__ f1W, const float* __restrict__ f1b,
                             const float* __restrict__ bf1g, const float* __restrict__ bf1b,
                             const float* __restrict__ bf1m, const float* __restrict__ bf1v,
                             const float* __restrict__ f2W, const float* __restrict__ f2b,
                             const float* __restrict__ bf2g, const float* __restrict__ bf2b,
                             const float* __restrict__ bf2m, const float* __restrict__ bf2v,
                             float* __restrict__ out) {
    int n = blockIdx.x;
    int p = blockIdx.y * 256 + threadIdx.x;

    float ch[HH * CC];
#pragma unroll
    for (int h = 0; h < HH; h++)
#pragma unroll
        for (int c = 0; c < CC; c++)
            ch[h * CC + c] = d_agg[(size_t)n * HF + h * FF + c * PIX + p]
                           + gat_b[h * FF + c * PIX + p];

    float gv[CC];
#pragma unroll
    for (int oc = 0; oc < CC; oc++) {
        float t = fc2b[oc];
#pragma unroll
        for (int k = 0; k < HH * CC; k++) t += fc2W[oc * (HH * CC) + k] * ch[k];
        float inv = b2g[oc] * rsqrtf(b2v[oc] + BEPS);
        gv[oc] = t * inv + b2b[oc] - b2m[oc] * inv + x[(size_t)n * FF + oc * PIX + p];
    }
    float f1[CC];
#pragma unroll
    for (int oc = 0; oc < CC; oc++) {
        float t = f1b[oc];
#pragma unroll
        for (int ic = 0; ic < CC; ic++) t += f1W[oc * CC + ic] * gv[ic];
        float inv = bf1g[oc] * rsqrtf(bf1v[oc] + BEPS);
        float val = t * inv + bf1b[oc] - bf1m[oc] * inv;
        f1[oc] = val > 0.0f ? val : 0.0f;
    }
#pragma unroll
    for (int oc = 0; oc < CC; oc++) {
        float t = f2b[oc];
#pragma unroll
        for (int ic = 0; ic < CC; ic++) t += f2W[oc * CC + ic] * f1[ic];
        float inv = bf2g[oc] * rsqrtf(bf2v[oc] + BEPS);
        float val = t * inv + bf2b[oc] - bf2m[oc] * inv;
        out[(size_t)n * FF + oc * PIX + p] = val + gv[oc];
    }
}

// ---------------- launch -----------------------------------------------------
extern "C" void kernel_launch(void* const* d_in, const int* in_sizes, int n_in,
                              void* d_out, int out_size) {
    const float* x     = (const float*)d_in[0];
    const int*   ei    = (const int*)d_in[1];
    const float* fc1W  = (const float*)d_in[2];
    const float* fc1b  = (const float*)d_in[3];
    const float* b1g   = (const float*)d_in[4];
    const float* b1b   = (const float*)d_in[5];
    const float* b1m   = (const float*)d_in[6];
    const float* b1v   = (const float*)d_in[7];
    const float* Wl    = (const float*)d_in[8];
    const float* bl    = (const float*)d_in[9];
    const float* Wr    = (const float*)d_in[10];
    const float* br    = (const float*)d_in[11];
    const float* att   = (const float*)d_in[12];
    const float* gat_b = (const float*)d_in[13];
    const float* fc2W  = (const float*)d_in[14];
    const float* fc2b  = (const float*)d_in[15];
    const float* b2g   = (const float*)d_in[16];
    const float* b2b   = (const float*)d_in[17];
    const float* b2m   = (const float*)d_in[18];
    const float* b2v   = (const float*)d_in[19];
    const float* f1W   = (const float*)d_in[20];
    const float* f1b   = (const float*)d_in[21];
    const float* bf1g  = (const float*)d_in[22];
    const float* bf1b  = (const float*)d_in[23];
    const float* bf1m  = (const float*)d_in[24];
    const float* bf1v  = (const float*)d_in[25];
    const float* f2W   = (const float*)d_in[26];
    const float* f2b   = (const float*)d_in[27];
    const float* bf2g  = (const float*)d_in[28];
    const float* bf2b  = (const float*)d_in[29];
    const float* bf2m  = (const float*)d_in[30];
    const float* bf2v  = (const float*)d_in[31];
    float* out = (float*)d_out;

    // One-time host-side resource setup (streams/events; no device memory).
    static cudaStream_t sB = nullptr, sC = nullptr;
    static cudaEvent_t evFork, evL, evFc1, evGemmR, evCsr;
    if (sB == nullptr) {
        cudaStreamCreateWithFlags(&sB, cudaStreamNonBlocking);
        cudaStreamCreateWithFlags(&sC, cudaStreamNonBlocking);
        cudaEventCreateWithFlags(&evFork,  cudaEventDisableTiming);
        cudaEventCreateWithFlags(&evL,     cudaEventDisableTiming);
        cudaEventCreateWithFlags(&evFc1,   cudaEventDisableTiming);
        cudaEventCreateWithFlags(&evGemmR, cudaEventDisableTiming);
        cudaEventCreateWithFlags(&evCsr,   cudaEventDisableTiming);
        cudaFuncSetAttribute(mmagemm_kernel, cudaFuncAttributeMaxDynamicSharedMemorySize, SMEM_TOTAL);
        cudaFuncSetAttribute(logits_softmax_agg_kernel, cudaFuncAttributeMaxDynamicSharedMemorySize, LS_SMEM);
    }

    // fork side streams off the capture (default) stream
    cudaEventRecord(evFork, 0);
    cudaStreamWaitEvent(sB, evFork, 0);
    cudaStreamWaitEvent(sC, evFork, 0);

    // side stream B: weight converts, then gemm_R
    wconv_kernel<<<(FF * HF) / (256 * 8), 256, 0, sB>>>(Wl, 0);
    cudaEventRecord(evL, sB);
    wconv_kernel<<<(FF * HF) / (256 * 8), 256, 0, sB>>>(Wr, 1);

    // side stream C: CSR build (only needed by logits)
    csr_kernel<<<1, NN, 0, sC>>>(ei);
    cudaEventRecord(evCsr, sC);

    // main stream: fc1, then gemm_L once Wl is converted
    fc1_bn_kernel<<<dim3(NN, 4), 256>>>(x, fc1W, fc1b, b1g, b1b, b1m, b1v);
    cudaEventRecord(evFc1, 0);
    cudaStreamWaitEvent(0, evL, 0);
    mmagemm_kernel<<<TILES_PER_GEMM, 128, SMEM_TOTAL>>>(bl, br, 0);

    // gemm_R on stream B (needs Wr convert [program order] + fc1)
    cudaStreamWaitEvent(sB, evFc1, 0);
    mmagemm_kernel<<<TILES_PER_GEMM, 128, SMEM_TOTAL, sB>>>(bl, br, 1);
    cudaEventRecord(evGemmR, sB);

    // join: fused edge stage needs gemm_L (program order), gemm_R and csr
    cudaStreamWaitEvent(0, evGemmR, 0);
    cudaStreamWaitEvent(0, evCsr, 0);
    logits_softmax_agg_kernel<<<NN, 256, LS_SMEM>>>(att);
    final_kernel<<<dim3(NN, 4), 256>>>(x, gat_b, fc2W, fc2b, b2g, b2b, b2m, b2v,
                                       f1W, f1b, bf1g, bf1b, bf1m, bf1v,
                                       f2W, f2b, bf2g, bf2b, bf2m, bf2v, out);
}